// round 15
// baseline (speedup 1.0000x reference)
#include <cuda_runtime.h>
#include <cstdint>

// EventMessagePassingEdge: out = relu([h[src]|e_h|h[dst]]@W1+b1 | ext] @ W2 + b2)
// Folded:  out = relu( P'[src] + Q[dst] + [e_h|ext] @ M )      (c folded into P')
// bf16 mma.sync m16n8k16 with 2-term split: A=A1+A2, B=B1+B2 (bf16),
//   D ~= A1B1 + A1B2 + A2B1 (fp32 accum).
// R15: edge = 384 thr / 96-edge tile / 12 warps (6m x 2n) / 3 CTAs-SM (occ 56%);
//   prep+split fused into one 1-CTA kernel; node kernel unchanged (R14).

#define N_NODES 50000
#define N_EDGES 800000
#define HID 64
#define EXT 32

typedef unsigned long long ull;
typedef unsigned int u32;

// ---- device scratch (no allocations allowed) ----
__device__ float g_P[N_NODES * HID];                 // h @ (W1a@W2a) + c
__device__ float g_Q[N_NODES * HID];                 // h @ (W1c@W2a)
__device__ float g_c[HID];                           // b1@W2a + b2
__device__ __align__(16) u32 g_Mb[2][64 * 52];       // edge B split, n-major [64][104 bf16]
__device__ __align__(16) u32 g_Wb[2][2][64 * 36];    // node B split [half][term], [64][72 bf16]

// ---- helpers ----
__device__ __forceinline__ u32 smem_u32(const void* p) {
    u32 a; asm("{ .reg .u64 t; cvta.to.shared.u64 t, %1; cvt.u32.u64 %0, t; }" : "=r"(a) : "l"(p));
    return a;
}
__device__ __forceinline__ void split2(float v0, float v1, u32& hi, u32& lo) {
    asm("cvt.rn.bf16x2.f32 %0, %1, %2;" : "=r"(hi) : "f"(v1), "f"(v0));   // lo16=v0, hi16=v1
    float h0 = __uint_as_float(hi << 16);
    float h1 = __uint_as_float(hi & 0xffff0000u);
    float r0 = v0 - h0, r1 = v1 - h1;
    asm("cvt.rn.bf16x2.f32 %0, %1, %2;" : "=r"(lo) : "f"(r1), "f"(r0));
}

// ---- mma.sync primitives ----
__device__ __forceinline__ void ldsm4(u32& r0, u32& r1, u32& r2, u32& r3, u32 addr) {
    asm volatile("ldmatrix.sync.aligned.m8n8.x4.shared.b16 {%0,%1,%2,%3}, [%4];"
                 : "=r"(r0), "=r"(r1), "=r"(r2), "=r"(r3) : "r"(addr));
}
__device__ __forceinline__ void mma16816(float* c, const u32* a, u32 b0, u32 b1) {
    asm volatile("mma.sync.aligned.m16n8k16.row.col.f32.bf16.bf16.f32 "
                 "{%0,%1,%2,%3}, {%4,%5,%6,%7}, {%8,%9}, {%0,%1,%2,%3};"
                 : "+f"(c[0]), "+f"(c[1]), "+f"(c[2]), "+f"(c[3])
                 : "r"(a[0]), "r"(a[1]), "r"(a[2]), "r"(a[3]), "r"(b0), "r"(b1));
}

// ---- Stage 0: fused weight fold + bf16 split (single CTA, all in smem) ----
// smem: sW2 [64][64] 16KB | sWn [64][128] 32KB | sM [96][64] 24KB = 72KB
__global__ void __launch_bounds__(1024) prep_kernel(const float* __restrict__ W1,
                                                    const float* __restrict__ b1,
                                                    const float* __restrict__ W2,
                                                    const float* __restrict__ b2) {
    extern __shared__ float ps[];
    float* sW2 = ps;                // [64][64]
    float* sWn = ps + 4096;         // [64][128]
    float* sM  = ps + 4096 + 8192;  // [96][64]
    int t = threadIdx.x;

    for (int i = t; i < 4096; i += 1024) sW2[i] = W2[i];
    __syncthreads();

    // 3 x 64 x 64 dot products: W1a@W2a -> Wn[:,0:64], W1c@W2a -> Wn[:,64:128], W1b@W2a -> M[0:64]
    for (int i = t; i < 3 * 4096; i += 1024) {
        int m = i >> 12;                          // 0:src 1:dst 2:e_h
        int k = (i >> 6) & 63, j = i & 63;
        int row = k + (m == 1 ? 128 : (m == 2 ? 64 : 0));
        const float* w1r = W1 + row * HID;
        float s = 0.f;
#pragma unroll 8
        for (int x = 0; x < 64; x++) s += w1r[x] * sW2[x * 64 + j];
        if (m == 0)      sWn[k * 128 + j] = s;
        else if (m == 1) sWn[k * 128 + 64 + j] = s;
        else             sM[k * 64 + j] = s;
    }
    for (int i = t; i < EXT * HID; i += 1024)     // W2b -> M rows 64..95
        sM[HID * HID + i] = W2[HID * HID + i];
    if (t < 64) {                                 // c = b1@W2a + b2
        float s = b2[t];
        for (int x = 0; x < 64; x++) s += b1[x] * sW2[x * 64 + t];
        g_c[t] = s;
    }
    __syncthreads();

    // split edge B = M^T (stride 52 u32) and node B = Wn^T (stride 36 u32)
    for (int i = t; i < 64 * 48; i += 1024) {
        int n = i & 63, kp = i >> 6;
        u32 hi, lo;
        split2(sM[(2 * kp) * 64 + n], sM[(2 * kp + 1) * 64 + n], hi, lo);
        g_Mb[0][n * 52 + kp] = hi;
        g_Mb[1][n * 52 + kp] = lo;
    }
    for (int i = t; i < 64 * 64; i += 1024) {
        int n = i & 63, rest = i >> 6;
        int kp = rest & 31, half = rest >> 5;
        u32 hi, lo;
        split2(sWn[(2 * kp) * 128 + half * 64 + n],
               sWn[(2 * kp + 1) * 128 + half * 64 + n], hi, lo);
        g_Wb[half][0][n * 36 + kp] = hi;
        g_Wb[half][1][n * 36 + kp] = lo;
    }
}

// ---- Stage 1: node precompute via bf16x3 mma (R14, unchanged) ----
#define NSTR 144
#define NOFF_A1 0
#define NOFF_A2 18432
#define NOFF_B1 36864
#define NOFF_B2 46080
#define NODE_SMEM 55296

__global__ void __launch_bounds__(512, 2) node_kernel(const float* __restrict__ h) {
    extern __shared__ char dynsmem[];
    char* smem = dynsmem;
    u32 sb = smem_u32(smem);
    int tid = threadIdx.x, wid = tid >> 5, lane = tid & 31;
    int nb = blockIdx.x * 128;
    int half = blockIdx.y;

    {
        const float4* h4 = (const float4*)h;
#pragma unroll
        for (int it = 0; it < 4; it++) {
            int f = tid + it * 512;
            int r = f >> 4, k4 = (f & 15) * 4;
            float4 v = make_float4(0.f, 0.f, 0.f, 0.f);
            if (nb + r < N_NODES) v = h4[(size_t)(nb + r) * 16 + (f & 15)];
            u32 off = (u32)(r * NSTR + k4 * 2);
            u32 h0, l0, h1, l1;
            split2(v.x, v.y, h0, l0);
            split2(v.z, v.w, h1, l1);
            *(ull*)(smem + NOFF_A1 + off) = (ull)h0 | ((ull)h1 << 32);
            *(ull*)(smem + NOFF_A2 + off) = (ull)l0 | ((ull)l1 << 32);
        }
        const float4* wb0 = (const float4*)g_Wb[half][0];
        const float4* wb1 = (const float4*)g_Wb[half][1];
#pragma unroll
        for (int it = 0; it < 2; it++) {
            int f = tid + it * 512;
            if (f < 576) {
                ((float4*)(smem + NOFF_B1))[f] = wb0[f];
                ((float4*)(smem + NOFF_B2))[f] = wb1[f];
            }
        }
    }
    __syncthreads();

    int wm = (wid & 7) * 16, wn = (wid >> 3) * 32;
    float acc[4][4];
#pragma unroll
    for (int nt = 0; nt < 4; nt++)
#pragma unroll
        for (int i = 0; i < 4; i++) acc[nt][i] = 0.f;

    u32 arow  = sb + (u32)((wm + (lane & 15)) * NSTR + (lane >> 4) * 16);
    u32 brow0 = sb + (u32)((wn + (lane & 15)) * NSTR + (lane >> 4) * 16);
    u32 brow1 = brow0 + 16 * NSTR;

#pragma unroll
    for (int c = 0; c < 4; c++) {
        u32 co = (u32)(c * 32);
        u32 a1[4], a2[4], b1[4][2], b2[4][2];
        ldsm4(a1[0], a1[1], a1[2], a1[3], arow + NOFF_A1 + co);
        ldsm4(a2[0], a2[1], a2[2], a2[3], arow + NOFF_A2 + co);
        {
            u32 m0, m1, m2, m3;
            ldsm4(m0, m1, m2, m3, brow0 + NOFF_B1 + co);
            b1[0][0] = m0; b1[0][1] = m2; b1[1][0] = m1; b1[1][1] = m3;
            ldsm4(m0, m1, m2, m3, brow1 + NOFF_B1 + co);
            b1[2][0] = m0; b1[2][1] = m2; b1[3][0] = m1; b1[3][1] = m3;
            ldsm4(m0, m1, m2, m3, brow0 + NOFF_B2 + co);
            b2[0][0] = m0; b2[0][1] = m2; b2[1][0] = m1; b2[1][1] = m3;
            ldsm4(m0, m1, m2, m3, brow1 + NOFF_B2 + co);
            b2[2][0] = m0; b2[2][1] = m2; b2[3][0] = m1; b2[3][1] = m3;
        }
#pragma unroll
        for (int nt = 0; nt < 4; nt++) {
            mma16816(acc[nt], a1, b1[nt][0], b1[nt][1]);
            mma16816(acc[nt], a1, b2[nt][0], b2[nt][1]);
            mma16816(acc[nt], a2, b1[nt][0], b1[nt][1]);
        }
    }
    __syncthreads();

    {
        int r0 = wm + (lane >> 2);
#pragma unroll
        for (int nt = 0; nt < 4; nt++) {
            int n0 = wn + nt * 8 + 2 * (lane & 3);
#pragma unroll
            for (int hh = 0; hh < 2; hh++) {
                int r = r0 + hh * 8;
                u32 off = (u32)(r * 256 + (((n0 >> 2) ^ (r & 7)) << 4) + (n0 & 3) * 4);
                *(float2*)(smem + off) = make_float2(acc[nt][hh * 2], acc[nt][hh * 2 + 1]);
            }
        }
    }
    __syncthreads();

    {
        float* outp = half ? g_Q : g_P;
#pragma unroll
        for (int it = 0; it < 4; it++) {
            int f = tid + it * 512;
            int r = f >> 4, c4 = f & 15;
            if (nb + r < N_NODES) {
                float4 v = *(const float4*)(smem + r * 256 + ((c4 ^ (r & 7)) << 4));
                if (half == 0) {
                    float4 cv = *(const float4*)(g_c + c4 * 4);
                    v.x += cv.x; v.y += cv.y; v.z += cv.z; v.w += cv.w;
                }
                *(float4*)(outp + (size_t)(nb + r) * 64 + c4 * 4) = v;
            }
        }
    }
}

// ---- Stage 2: edge kernel — 384 thr, 96-edge tile, 12 warps (6m x 2n), 3 CTAs/SM ----
// smem: A1@0 (96x208=19968), A2@19968, B1@39936 (13312), B2@53248, idx@66560 (768)
// staging (f32 96x64 = 24576B, XOR-staggered) overlays A1/A2 after MMA.
#define ASTR 208
#define OFF_A1 0
#define OFF_A2 19968
#define OFF_B1 39936
#define OFF_B2 53248
#define OFF_IDX 66560
#define EDGE_SMEM 67328

__global__ void __launch_bounds__(384, 3) edge_kernel(const float* __restrict__ e_h,
                                                      const float* __restrict__ ext,
                                                      const int* __restrict__ src,
                                                      const int* __restrict__ dst,
                                                      float* __restrict__ out) {
    extern __shared__ char dynsmem[];
    char* smem = dynsmem;
    u32 sb = smem_u32(smem);
    int tid = threadIdx.x, wid = tid >> 5, lane = tid & 31;
    size_t ebase = (size_t)blockIdx.x * 96;
    int* sidx = (int*)(smem + OFF_IDX);
    int* didx = sidx + 96;

    if (tid < 96) sidx[tid] = (ebase + tid < N_EDGES) ? src[ebase + tid] : 0;
    else if (tid < 192) {
        int r = tid - 96;
        didx[r] = (ebase + r < N_EDGES) ? dst[ebase + r] : 0;
    }

    // -- stage A: load fp32 (guarded), split into bf16 hi/lo tiles --
    {
        const float4* g4 = (const float4*)(e_h + ebase * 64);     // k 0..63
#pragma unroll
        for (int it = 0; it < 4; it++) {
            int f = tid + it * 384;
            int r = f >> 4, k4 = (f & 15) * 4;
            float4 v = make_float4(0.f, 0.f, 0.f, 0.f);
            if (ebase + r < N_EDGES) v = g4[f];
            u32 off = (u32)(r * ASTR + k4 * 2);
            u32 h0, l0, h1, l1;
            split2(v.x, v.y, h0, l0);
            split2(v.z, v.w, h1, l1);
            *(ull*)(smem + OFF_A1 + off) = (ull)h0 | ((ull)h1 << 32);
            *(ull*)(smem + OFF_A2 + off) = (ull)l0 | ((ull)l1 << 32);
        }
        const float4* x4 = (const float4*)(ext + ebase * 32);     // k 64..95
#pragma unroll
        for (int it = 0; it < 2; it++) {
            int f = tid + it * 384;
            int r = f >> 3, k4 = 64 + (f & 7) * 4;
            float4 v = make_float4(0.f, 0.f, 0.f, 0.f);
            if (ebase + r < N_EDGES) v = x4[f];
            u32 off = (u32)(r * ASTR + k4 * 2);
            u32 h0, l0, h1, l1;
            split2(v.x, v.y, h0, l0);
            split2(v.z, v.w, h1, l1);
            *(ull*)(smem + OFF_A1 + off) = (ull)h0 | ((ull)h1 << 32);
            *(ull*)(smem + OFF_A2 + off) = (ull)l0 | ((ull)l1 << 32);
        }
        const float4* mb0 = (const float4*)g_Mb[0];
        const float4* mb1 = (const float4*)g_Mb[1];
#pragma unroll
        for (int it = 0; it < 3; it++) {
            int f = tid + it * 384;
            if (f < 832) {
                ((float4*)(smem + OFF_B1))[f] = mb0[f];
                ((float4*)(smem + OFF_B2))[f] = mb1[f];
            }
        }
    }
    __syncthreads();

    // -- MMA mainloop: 12 warps 6m x 2n; warp tile 16x32; fused 3-term per k16 --
    int wm = (wid % 6) * 16, wn = (wid / 6) * 32;
    float acc[4][4];
#pragma unroll
    for (int nt = 0; nt < 4; nt++)
#pragma unroll
        for (int i = 0; i < 4; i++) acc[nt][i] = 0.f;

    u32 arow  = sb + (u32)((wm + (lane & 15)) * ASTR + (lane >> 4) * 16);
    u32 brow0 = sb + (u32)((wn + (lane & 15)) * ASTR + (lane >> 4) * 16);
    u32 brow1 = brow0 + 16 * ASTR;

#pragma unroll
    for (int c = 0; c < 6; c++) {
        u32 co = (u32)(c * 32);
        u32 a1[4], a2[4], b1[4][2], b2[4][2];
        ldsm4(a1[0], a1[1], a1[2], a1[3], arow + OFF_A1 + co);
        ldsm4(a2[0], a2[1], a2[2], a2[3], arow + OFF_A2 + co);
        {
            u32 m0, m1, m2, m3;
            ldsm4(m0, m1, m2, m3, brow0 + OFF_B1 + co);
            b1[0][0] = m0; b1[0][1] = m2; b1[1][0] = m1; b1[1][1] = m3;
            ldsm4(m0, m1, m2, m3, brow1 + OFF_B1 + co);
            b1[2][0] = m0; b1[2][1] = m2; b1[3][0] = m1; b1[3][1] = m3;
            ldsm4(m0, m1, m2, m3, brow0 + OFF_B2 + co);
            b2[0][0] = m0; b2[0][1] = m2; b2[1][0] = m1; b2[1][1] = m3;
            ldsm4(m0, m1, m2, m3, brow1 + OFF_B2 + co);
            b2[2][0] = m0; b2[2][1] = m2; b2[3][0] = m1; b2[3][1] = m3;
        }
#pragma unroll
        for (int nt = 0; nt < 4; nt++) {
            mma16816(acc[nt], a1, b1[nt][0], b1[nt][1]);
            mma16816(acc[nt], a1, b2[nt][0], b2[nt][1]);
            mma16816(acc[nt], a2, b1[nt][0], b1[nt][1]);
        }
    }
    __syncthreads();   // A/B smem dead; staging overlays it

    // -- write accs to f32 staging (XOR-staggered 16B chunks per row) --
    {
        int r0 = wm + (lane >> 2);
#pragma unroll
        for (int nt = 0; nt < 4; nt++) {
            int n0 = wn + nt * 8 + 2 * (lane & 3);
#pragma unroll
            for (int hh = 0; hh < 2; hh++) {
                int r = r0 + hh * 8;
                u32 off = (u32)(r * 256 + (((n0 >> 2) ^ (r & 7)) << 4) + (n0 & 3) * 4);
                *(float2*)(smem + off) = make_float2(acc[nt][hh * 2], acc[nt][hh * 2 + 1]);
            }
        }
    }
    __syncthreads();

    // -- coalesced epilogue: stage + P'[src] + Q[dst], relu, store (guarded) --
    {
        float4* o4 = (float4*)(out + ebase * 64);
#pragma unroll
        for (int it = 0; it < 4; it++) {
            int f = tid + it * 384;
            int r = f >> 4, c4 = f & 15;
            if (ebase + r < N_EDGES) {
                float4 v = *(const float4*)(smem + r * 256 + ((c4 ^ (r & 7)) << 4));
                int s = sidx[r], d = didx[r];
                float4 p = *(const float4*)(g_P + (size_t)s * 64 + c4 * 4);
                float4 q = *(const float4*)(g_Q + (size_t)d * 64 + c4 * 4);
                float4 o;
                o.x = fmaxf(v.x + p.x + q.x, 0.f);
                o.y = fmaxf(v.y + p.y + q.y, 0.f);
                o.z = fmaxf(v.z + p.z + q.z, 0.f);
                o.w = fmaxf(v.w + p.w + q.w, 0.f);
                o4[f] = o;
            }
        }
    }
}

extern "C" void kernel_launch(void* const* d_in, const int* in_sizes, int n_in,
                              void* d_out, int out_size) {
    const float* h    = (const float*)d_in[0];
    const float* e_h  = (const float*)d_in[1];
    const float* extf = (const float*)d_in[2];
    const float* W1   = (const float*)d_in[3];
    const float* b1   = (const float*)d_in[4];
    const float* W2   = (const float*)d_in[5];
    const float* b2   = (const float*)d_in[6];
    const int* src    = (const int*)d_in[7];
    const int* dst    = (const int*)d_in[8];
    float* out = (float*)d_out;

    const int prep_smem = (4096 + 8192 + 6144) * 4;   // 73728 B
    cudaFuncSetAttribute(prep_kernel, cudaFuncAttributeMaxDynamicSharedMemorySize, prep_smem);
    cudaFuncSetAttribute(node_kernel, cudaFuncAttributeMaxDynamicSharedMemorySize, NODE_SMEM);
    cudaFuncSetAttribute(edge_kernel, cudaFuncAttributeMaxDynamicSharedMemorySize, EDGE_SMEM);

    prep_kernel<<<1, 1024, prep_smem>>>(W1, b1, W2, b2);
    node_kernel<<<dim3((N_NODES + 127) / 128, 2), 512, NODE_SMEM>>>(h);
    edge_kernel<<<(N_EDGES + 95) / 96, 384, EDGE_SMEM>>>(e_h, extf, src, dst, out);
}

// round 16
// speedup vs baseline: 1.1122x; 1.1122x over previous
#include <cuda_runtime.h>
#include <cstdint>

// EventMessagePassingEdge: out = relu([h[src]|e_h|h[dst]]@W1+b1 | ext] @ W2 + b2)
// Folded:  out = relu( P'[src] + Q[dst] + [e_h|ext] @ M )      (c folded into P')
// bf16 mma.sync m16n8k16 with 2-term split: A=A1+A2, B=B1+B2 (bf16),
//   D ~= A1B1 + A1B2 + A2B1 (fp32 accum).
// R16: edge loads A fragments DIRECTLY from global (no A smem/STS/ldmatrix —
//   -14% L1 wavefronts), smem 81KB -> 34KB; prep+split fused into one parallel
//   kernel (R15's 1-CTA prep was a 44us serial disaster); node kernel = R14.

#define N_NODES 50000
#define N_EDGES 800000
#define HID 64
#define EXT 32

typedef unsigned long long ull;
typedef unsigned int u32;

// ---- device scratch (no allocations allowed) ----
__device__ float g_P[N_NODES * HID];                 // h @ (W1a@W2a) + c
__device__ float g_Q[N_NODES * HID];                 // h @ (W1c@W2a)
__device__ float g_c[HID];                           // b1@W2a + b2
__device__ __align__(16) u32 g_Mb[2][64 * 52];       // edge B split, n-major [64][104 bf16]
__device__ __align__(16) u32 g_Wb[2][2][64 * 36];    // node B split [half][term], [64][72 bf16]

// ---- helpers ----
__device__ __forceinline__ u32 smem_u32(const void* p) {
    u32 a; asm("{ .reg .u64 t; cvta.to.shared.u64 t, %1; cvt.u32.u64 %0, t; }" : "=r"(a) : "l"(p));
    return a;
}
__device__ __forceinline__ void split2(float v0, float v1, u32& hi, u32& lo) {
    asm("cvt.rn.bf16x2.f32 %0, %1, %2;" : "=r"(hi) : "f"(v1), "f"(v0));   // lo16=v0, hi16=v1
    float h0 = __uint_as_float(hi << 16);
    float h1 = __uint_as_float(hi & 0xffff0000u);
    float r0 = v0 - h0, r1 = v1 - h1;
    asm("cvt.rn.bf16x2.f32 %0, %1, %2;" : "=r"(lo) : "f"(r1), "f"(r0));
}

// ---- mma.sync primitives ----
__device__ __forceinline__ void ldsm4(u32& r0, u32& r1, u32& r2, u32& r3, u32 addr) {
    asm volatile("ldmatrix.sync.aligned.m8n8.x4.shared.b16 {%0,%1,%2,%3}, [%4];"
                 : "=r"(r0), "=r"(r1), "=r"(r2), "=r"(r3) : "r"(addr));
}
__device__ __forceinline__ void mma16816(float* c, const u32* a, u32 b0, u32 b1) {
    asm volatile("mma.sync.aligned.m16n8k16.row.col.f32.bf16.bf16.f32 "
                 "{%0,%1,%2,%3}, {%4,%5,%6,%7}, {%8,%9}, {%0,%1,%2,%3};"
                 : "+f"(c[0]), "+f"(c[1]), "+f"(c[2]), "+f"(c[3])
                 : "r"(a[0]), "r"(a[1]), "r"(a[2]), "r"(a[3]), "r"(b0), "r"(b1));
}

// ---- Stage 0: fused fold + split (parallel; each thread: dot-pair -> split) ----
// tasks (t = global thread, 7232 total):
//   [0,2048):     edge B kp 0..31   = (W1b@W2a) pairs -> g_Mb
//   [2048,6144):  node B            = (W1a/W1c@W2a) pairs -> g_Wb
//   [6144,7168):  edge B kp 32..47  = W2b pairs (copy+split) -> g_Mb
//   [7168,7232):  c = b1@W2a + b2
__global__ void __launch_bounds__(128) prep_kernel(const float* __restrict__ W1,
                                                   const float* __restrict__ b1,
                                                   const float* __restrict__ W2,
                                                   const float* __restrict__ b2) {
    __shared__ float sW2[64 * 64];
    for (int i = threadIdx.x; i < 4096; i += 128) sW2[i] = W2[i];
    __syncthreads();
    int t = blockIdx.x * 128 + threadIdx.x;

    if (t < 2048) {                                   // edge B computed half
        int n = t & 63, kp = t >> 6;
        const float* ra = W1 + (64 + 2 * kp) * HID;
        const float* rb = ra + HID;
        float v0 = 0.f, v1 = 0.f;
#pragma unroll 8
        for (int x = 0; x < 64; x++) {
            float w = sW2[x * 64 + n];
            v0 += ra[x] * w;
            v1 += rb[x] * w;
        }
        u32 hi, lo;
        split2(v0, v1, hi, lo);
        g_Mb[0][n * 52 + kp] = hi;
        g_Mb[1][n * 52 + kp] = lo;
    } else if (t < 6144) {                            // node B
        int u = t - 2048;
        int n = u & 63, kp = (u >> 6) & 31, half = u >> 11;
        const float* ra = W1 + ((half ? 128 : 0) + 2 * kp) * HID;
        const float* rb = ra + HID;
        float v0 = 0.f, v1 = 0.f;
#pragma unroll 8
        for (int x = 0; x < 64; x++) {
            float w = sW2[x * 64 + n];
            v0 += ra[x] * w;
            v1 += rb[x] * w;
        }
        u32 hi, lo;
        split2(v0, v1, hi, lo);
        g_Wb[half][0][n * 36 + kp] = hi;
        g_Wb[half][1][n * 36 + kp] = lo;
    } else if (t < 7168) {                            // edge B from W2b
        int u = t - 6144;
        int n = u & 63, kp = 32 + (u >> 6);
        float v0 = W2[(2 * kp) * 64 + n];
        float v1 = W2[(2 * kp + 1) * 64 + n];
        u32 hi, lo;
        split2(v0, v1, hi, lo);
        g_Mb[0][n * 52 + kp] = hi;
        g_Mb[1][n * 52 + kp] = lo;
    } else if (t < 7232) {                            // c
        int j = t - 7168;
        float s = b2[j];
        for (int x = 0; x < 64; x++) s += b1[x] * sW2[x * 64 + j];
        g_c[j] = s;
    }
}

// ---- Stage 1: node precompute via bf16x3 mma (R14, unchanged) ----
#define NSTR 144
#define NOFF_A1 0
#define NOFF_A2 18432
#define NOFF_B1 36864
#define NOFF_B2 46080
#define NODE_SMEM 55296

__global__ void __launch_bounds__(512, 2) node_kernel(const float* __restrict__ h) {
    extern __shared__ char dynsmem[];
    char* smem = dynsmem;
    u32 sb = smem_u32(smem);
    int tid = threadIdx.x, wid = tid >> 5, lane = tid & 31;
    int nb = blockIdx.x * 128;
    int half = blockIdx.y;

    {
        const float4* h4 = (const float4*)h;
#pragma unroll
        for (int it = 0; it < 4; it++) {
            int f = tid + it * 512;
            int r = f >> 4, k4 = (f & 15) * 4;
            float4 v = make_float4(0.f, 0.f, 0.f, 0.f);
            if (nb + r < N_NODES) v = h4[(size_t)(nb + r) * 16 + (f & 15)];
            u32 off = (u32)(r * NSTR + k4 * 2);
            u32 h0, l0, h1, l1;
            split2(v.x, v.y, h0, l0);
            split2(v.z, v.w, h1, l1);
            *(ull*)(smem + NOFF_A1 + off) = (ull)h0 | ((ull)h1 << 32);
            *(ull*)(smem + NOFF_A2 + off) = (ull)l0 | ((ull)l1 << 32);
        }
        const float4* wb0 = (const float4*)g_Wb[half][0];
        const float4* wb1 = (const float4*)g_Wb[half][1];
#pragma unroll
        for (int it = 0; it < 2; it++) {
            int f = tid + it * 512;
            if (f < 576) {
                ((float4*)(smem + NOFF_B1))[f] = wb0[f];
                ((float4*)(smem + NOFF_B2))[f] = wb1[f];
            }
        }
    }
    __syncthreads();

    int wm = (wid & 7) * 16, wn = (wid >> 3) * 32;
    float acc[4][4];
#pragma unroll
    for (int nt = 0; nt < 4; nt++)
#pragma unroll
        for (int i = 0; i < 4; i++) acc[nt][i] = 0.f;

    u32 arow  = sb + (u32)((wm + (lane & 15)) * NSTR + (lane >> 4) * 16);
    u32 brow0 = sb + (u32)((wn + (lane & 15)) * NSTR + (lane >> 4) * 16);
    u32 brow1 = brow0 + 16 * NSTR;

#pragma unroll
    for (int c = 0; c < 4; c++) {
        u32 co = (u32)(c * 32);
        u32 a1[4], a2[4], b1[4][2], b2[4][2];
        ldsm4(a1[0], a1[1], a1[2], a1[3], arow + NOFF_A1 + co);
        ldsm4(a2[0], a2[1], a2[2], a2[3], arow + NOFF_A2 + co);
        {
            u32 m0, m1, m2, m3;
            ldsm4(m0, m1, m2, m3, brow0 + NOFF_B1 + co);
            b1[0][0] = m0; b1[0][1] = m2; b1[1][0] = m1; b1[1][1] = m3;
            ldsm4(m0, m1, m2, m3, brow1 + NOFF_B1 + co);
            b1[2][0] = m0; b1[2][1] = m2; b1[3][0] = m1; b1[3][1] = m3;
            ldsm4(m0, m1, m2, m3, brow0 + NOFF_B2 + co);
            b2[0][0] = m0; b2[0][1] = m2; b2[1][0] = m1; b2[1][1] = m3;
            ldsm4(m0, m1, m2, m3, brow1 + NOFF_B2 + co);
            b2[2][0] = m0; b2[2][1] = m2; b2[3][0] = m1; b2[3][1] = m3;
        }
#pragma unroll
        for (int nt = 0; nt < 4; nt++) {
            mma16816(acc[nt], a1, b1[nt][0], b1[nt][1]);
            mma16816(acc[nt], a1, b2[nt][0], b2[nt][1]);
            mma16816(acc[nt], a2, b1[nt][0], b1[nt][1]);
        }
    }
    __syncthreads();

    {
        int r0 = wm + (lane >> 2);
#pragma unroll
        for (int nt = 0; nt < 4; nt++) {
            int n0 = wn + nt * 8 + 2 * (lane & 3);
#pragma unroll
            for (int hh = 0; hh < 2; hh++) {
                int r = r0 + hh * 8;
                u32 off = (u32)(r * 256 + (((n0 >> 2) ^ (r & 7)) << 4) + (n0 & 3) * 4);
                *(float2*)(smem + off) = make_float2(acc[nt][hh * 2], acc[nt][hh * 2 + 1]);
            }
        }
    }
    __syncthreads();

    {
        float* outp = half ? g_Q : g_P;
#pragma unroll
        for (int it = 0; it < 4; it++) {
            int f = tid + it * 512;
            int r = f >> 4, c4 = f & 15;
            if (nb + r < N_NODES) {
                float4 v = *(const float4*)(smem + r * 256 + ((c4 ^ (r & 7)) << 4));
                if (half == 0) {
                    float4 cv = *(const float4*)(g_c + c4 * 4);
                    v.x += cv.x; v.y += cv.y; v.z += cv.z; v.w += cv.w;
                }
                *(float4*)(outp + (size_t)(nb + r) * 64 + c4 * 4) = v;
            }
        }
    }
}

// ---- Stage 2: edge kernel — A fragments direct from gmem; B in smem ----
// smem: staging f32 [128][256B] @0 (32768) overlays B1@0 (13312) + B2@13312
// (13312) which die at the post-mainloop sync; idx @32768 (1024). Total 33792.
#define OFF_B1 0
#define OFF_B2 13312
#define OFF_IDX 32768
#define EDGE_SMEM 33792

__global__ void __launch_bounds__(512, 2) edge_kernel(const float* __restrict__ e_h,
                                                      const float* __restrict__ ext,
                                                      const int* __restrict__ src,
                                                      const int* __restrict__ dst,
                                                      float* __restrict__ out) {
    extern __shared__ char dynsmem[];
    char* smem = dynsmem;
    u32 sb = smem_u32(smem);
    int tid = threadIdx.x, wid = tid >> 5, lane = tid & 31;
    size_t ebase = (size_t)blockIdx.x * 128;
    int* sidx = (int*)(smem + OFF_IDX);
    int* didx = sidx + 128;

    if (tid < 128) sidx[tid] = src[ebase + tid];
    else if (tid < 256) didx[tid - 128] = dst[ebase + (tid - 128)];

    // stage B (only smem producer in prologue)
    {
        const float4* mb0 = (const float4*)g_Mb[0];
        const float4* mb1 = (const float4*)g_Mb[1];
#pragma unroll
        for (int it = 0; it < 2; it++) {
            int f = tid + it * 512;
            if (f < 832) {
                ((float4*)(smem + OFF_B1))[f] = mb0[f];
                ((float4*)(smem + OFF_B2))[f] = mb1[f];
            }
        }
    }

    int wm = (wid & 7) * 16, wn = (wid >> 3) * 32;
    // per-thread A fragment base pointers (row = wm + lane/4, col = (lane%4)*2)
    const float* pe = e_h + (ebase + wm + (lane >> 2)) * 64 + (lane & 3) * 2;
    const float* px = ext + (ebase + wm + (lane >> 2)) * 32 + (lane & 3) * 2;

    float acc[4][4];
#pragma unroll
    for (int nt = 0; nt < 4; nt++)
#pragma unroll
        for (int i = 0; i < 4; i++) acc[nt][i] = 0.f;

    __syncthreads();

    u32 brow0 = sb + (u32)((wn + (lane & 15)) * 208 + (lane >> 4) * 16);
    u32 brow1 = brow0 + 16 * 208;

#pragma unroll
    for (int c = 0; c < 6; c++) {
        // A fragments direct from global, split in registers
        const float* p = (c < 4) ? pe : px;
        int stride = (c < 4) ? 64 : 32;
        int cb = (c < 4) ? c * 16 : (c - 4) * 16;
        float2 f0 = *(const float2*)(p + cb);
        float2 f1 = *(const float2*)(p + cb + 8 * stride);
        float2 f2 = *(const float2*)(p + cb + 8);
        float2 f3 = *(const float2*)(p + cb + 8 * stride + 8);
        u32 a1[4], a2[4];
        split2(f0.x, f0.y, a1[0], a2[0]);
        split2(f1.x, f1.y, a1[1], a2[1]);
        split2(f2.x, f2.y, a1[2], a2[2]);
        split2(f3.x, f3.y, a1[3], a2[3]);

        u32 co = (u32)(c * 32);
        u32 b1[4][2], b2[4][2];
        {
            u32 m0, m1, m2, m3;
            ldsm4(m0, m1, m2, m3, brow0 + OFF_B1 + co);
            b1[0][0] = m0; b1[0][1] = m2; b1[1][0] = m1; b1[1][1] = m3;
            ldsm4(m0, m1, m2, m3, brow1 + OFF_B1 + co);
            b1[2][0] = m0; b1[2][1] = m2; b1[3][0] = m1; b1[3][1] = m3;
            ldsm4(m0, m1, m2, m3, brow0 + OFF_B2 + co);
            b2[0][0] = m0; b2[0][1] = m2; b2[1][0] = m1; b2[1][1] = m3;
            ldsm4(m0, m1, m2, m3, brow1 + OFF_B2 + co);
            b2[2][0] = m0; b2[2][1] = m2; b2[3][0] = m1; b2[3][1] = m3;
        }
#pragma unroll
        for (int nt = 0; nt < 4; nt++) {
            mma16816(acc[nt], a1, b1[nt][0], b1[nt][1]);
            mma16816(acc[nt], a1, b2[nt][0], b2[nt][1]);
            mma16816(acc[nt], a2, b1[nt][0], b1[nt][1]);
        }
    }
    __syncthreads();   // B smem dead; staging overlays it

    // write accs to f32 staging (XOR-staggered 16B chunks per row)
    {
        int r0 = wm + (lane >> 2);
#pragma unroll
        for (int nt = 0; nt < 4; nt++) {
            int n0 = wn + nt * 8 + 2 * (lane & 3);
#pragma unroll
            for (int hh = 0; hh < 2; hh++) {
                int r = r0 + hh * 8;
                u32 off = (u32)(r * 256 + (((n0 >> 2) ^ (r & 7)) << 4) + (n0 & 3) * 4);
                *(float2*)(smem + off) = make_float2(acc[nt][hh * 2], acc[nt][hh * 2 + 1]);
            }
        }
    }
    __syncthreads();

    // coalesced epilogue: stage + P'[src] + Q[dst], relu, store
    {
        float4* o4 = (float4*)(out + ebase * 64);
#pragma unroll
        for (int it = 0; it < 4; it++) {
            int f = tid + it * 512;
            int r = f >> 4, c4 = f & 15;
            float4 v = *(const float4*)(smem + r * 256 + ((c4 ^ (r & 7)) << 4));
            int s = sidx[r], d = didx[r];
            float4 p = *(const float4*)(g_P + (size_t)s * 64 + c4 * 4);
            float4 q = *(const float4*)(g_Q + (size_t)d * 64 + c4 * 4);
            float4 o;
            o.x = fmaxf(v.x + p.x + q.x, 0.f);
            o.y = fmaxf(v.y + p.y + q.y, 0.f);
            o.z = fmaxf(v.z + p.z + q.z, 0.f);
            o.w = fmaxf(v.w + p.w + q.w, 0.f);
            o4[f] = o;
        }
    }
}

extern "C" void kernel_launch(void* const* d_in, const int* in_sizes, int n_in,
                              void* d_out, int out_size) {
    const float* h    = (const float*)d_in[0];
    const float* e_h  = (const float*)d_in[1];
    const float* extf = (const float*)d_in[2];
    const float* W1   = (const float*)d_in[3];
    const float* b1   = (const float*)d_in[4];
    const float* W2   = (const float*)d_in[5];
    const float* b2   = (const float*)d_in[6];
    const int* src    = (const int*)d_in[7];
    const int* dst    = (const int*)d_in[8];
    float* out = (float*)d_out;

    cudaFuncSetAttribute(node_kernel, cudaFuncAttributeMaxDynamicSharedMemorySize, NODE_SMEM);
    cudaFuncSetAttribute(edge_kernel, cudaFuncAttributeMaxDynamicSharedMemorySize, EDGE_SMEM);

    prep_kernel<<<57, 128>>>(W1, b1, W2, b2);
    node_kernel<<<dim3((N_NODES + 127) / 128, 2), 512, NODE_SMEM>>>(h);
    edge_kernel<<<N_EDGES / 128, 512, EDGE_SMEM>>>(e_h, extf, src, dst, out);
}